// round 1
// baseline (speedup 1.0000x reference)
#include <cuda_runtime.h>
#include <cstdint>

#define N_NODES 50000
#define N_EDGES 800000
#define DIM 64
#define HID 128
#define DT 0.1f
#define TAU 2.0f
#define LAMBDA_W 1e-4f
#define N_STEPS 10

// ---------------- scratch (device globals; no allocations allowed) ----------------
__device__ float g_x[N_NODES * DIM];
__device__ float g_e[N_NODES * DIM];
__device__ float g_msg[N_NODES * DIM];
__device__ float g_w[N_EDGES];
__device__ int2  g_edge[N_EDGES];
__device__ int   g_is64;

// ---------------- dtype detection for edge_index (int32 vs int64) -----------------
// For int64 data (values < 50000) every odd 32-bit word is 0. For int32 data the
// odd words are random node ids in [0, 50000) -> P(all 32 samples zero) ~ 0.
__global__ void detect_kernel(const int* __restrict__ ei32) {
    int v = ei32[2 * threadIdx.x + 1];
    unsigned nz = __ballot_sync(0xffffffffu, v != 0);
    if (threadIdx.x == 0) g_is64 = (nz == 0u) ? 1 : 0;
}

__global__ void convert_kernel(const void* __restrict__ ei, const float* __restrict__ w_in) {
    int i = blockIdx.x * blockDim.x + threadIdx.x;
    if (i >= N_EDGES) return;
    int s, t;
    if (g_is64) {
        const long long* p = (const long long*)ei;
        s = (int)p[i];
        t = (int)p[N_EDGES + i];
    } else {
        const int* p = (const int*)ei;
        s = p[i];
        t = p[N_EDGES + i];
    }
    g_edge[i] = make_int2(s, t);
    g_w[i] = w_in[i];
}

__global__ void init_nodes_kernel(const float* __restrict__ x_in) {
    int i = blockIdx.x * blockDim.x + threadIdx.x;
    if (i < N_NODES * DIM) {
        g_x[i] = x_in[i];
        g_e[i] = 0.0f;
        g_msg[i] = 0.0f;
    }
}

// ---------------- fused edge kernel: plasticity (step t) + messages (step t+1) ----
// 16 threads per edge, each owns 4 dims (float4). 2 edges per warp.
template <bool PLAST, bool MSG>
__global__ void __launch_bounds__(256) edge_kernel(const float* __restrict__ etap,
                                                   const float* __restrict__ etam) {
    int gt = blockIdx.x * 256 + threadIdx.x;
    int eidx = gt >> 4;  // grid sized exactly: N_EDGES*16 threads
    int sub = gt & 15;

    int2 st = g_edge[eidx];
    float w = g_w[eidx];
    const float4* x4 = (const float4*)g_x;
    float4 xs = x4[st.x * 16 + sub];
    float wn = w;

    if (PLAST) {
        const float4* e4 = (const float4*)g_e;
        float4 xt = x4[st.y * 16 + sub];
        float4 es = e4[st.x * 16 + sub];
        float4 et = e4[st.y * 16 + sub];
        float pp = xs.x * et.x + xs.y * et.y + xs.z * et.z + xs.w * et.w;
        float pm = xt.x * es.x + xt.y * es.y + xt.z * es.z + xt.w * es.w;
#pragma unroll
        for (int o = 8; o > 0; o >>= 1) {
            pp += __shfl_xor_sync(0xffffffffu, pp, o);
            pm += __shfl_xor_sync(0xffffffffu, pm, o);
        }
        float ep = __ldg(etap);
        float em = __ldg(etam);
        wn = w + DT * (ep * pp - em * pm - LAMBDA_W * w);
        if (sub == 0) g_w[eidx] = wn;
    }

    if (MSG) {
        float* dst = &g_msg[st.y * DIM + sub * 4];
        asm volatile("red.global.add.v4.f32 [%0], {%1,%2,%3,%4};"
                     :: "l"(dst), "f"(wn * xs.x), "f"(wn * xs.y),
                        "f"(wn * xs.z), "f"(wn * xs.w)
                     : "memory");
    }
}

// ---------------- node kernel: fused concat + MLP + x/e integration ----------------
// 128 nodes per block, 512 threads. Weights + activations in smem.
#define NT 128
#define NTH 512
#define SH_PAD 132  // 128 + 4 pad: avoids bank conflicts across node rows
#define SMEM_FLOATS (HID * HID + HID * DIM + HID + DIM + NT * SH_PAD + NT * DIM)
#define SMEM_BYTES (SMEM_FLOATS * 4)

__global__ void __launch_bounds__(NTH) node_kernel(const float* __restrict__ W1,
                                                   const float* __restrict__ b1,
                                                   const float* __restrict__ W2,
                                                   const float* __restrict__ b2) {
    extern __shared__ float smem[];
    float* sW1 = smem;                  // [128][128]
    float* sW2 = sW1 + HID * HID;       // [128][64]
    float* sB1 = sW2 + HID * DIM;       // [128]
    float* sB2 = sB1 + HID;             // [64]
    float* sH  = sB2 + DIM;             // [NT][132]  (input h, then reused for hidden)
    float* sF  = sH + NT * SH_PAD;      // [NT][64]

    int tid = threadIdx.x;
    int base = blockIdx.x * NT;

    // load weights (coalesced float4)
    {
        const float4* s4 = (const float4*)W1;
        float4* d4 = (float4*)sW1;
        for (int i = tid; i < HID * HID / 4; i += NTH) d4[i] = s4[i];
        const float4* s2 = (const float4*)W2;
        float4* d2 = (float4*)sW2;
        for (int i = tid; i < HID * DIM / 4; i += NTH) d2[i] = s2[i];
        if (tid < HID) sB1[tid] = b1[tid];
        else if (tid >= HID && tid < HID + DIM) sB2[tid - HID] = b2[tid - HID];
    }

    // load h = [x_i | msg_i]
    for (int i = tid; i < NT * HID; i += NTH) {
        int n = i >> 7;
        int c = i & 127;
        int node = base + n;
        float v = 0.0f;
        if (node < N_NODES)
            v = (c < DIM) ? g_x[node * DIM + c] : g_msg[node * DIM + (c - DIM)];
        sH[n * SH_PAD + c] = v;
    }
    __syncthreads();

    int jg = tid & 15;   // hidden-col group: 8 cols
    int ng = tid >> 4;   // node group: 4 nodes
    int j0 = jg * 8;
    int n0 = ng * 4;

    // ---- layer 1: hidden = relu(h @ W1 + b1) ----
    float acc[4][8];
#pragma unroll
    for (int i = 0; i < 4; i++)
#pragma unroll
        for (int u = 0; u < 8; u++) acc[i][u] = sB1[j0 + u];

#pragma unroll 4
    for (int k = 0; k < HID; k++) {
        float a0 = sH[(n0 + 0) * SH_PAD + k];
        float a1 = sH[(n0 + 1) * SH_PAD + k];
        float a2 = sH[(n0 + 2) * SH_PAD + k];
        float a3 = sH[(n0 + 3) * SH_PAD + k];
        float4 wA = *(const float4*)&sW1[k * HID + j0];
        float4 wB = *(const float4*)&sW1[k * HID + j0 + 4];
        float a[4] = {a0, a1, a2, a3};
#pragma unroll
        for (int i = 0; i < 4; i++) {
            acc[i][0] += a[i] * wA.x; acc[i][1] += a[i] * wA.y;
            acc[i][2] += a[i] * wA.z; acc[i][3] += a[i] * wA.w;
            acc[i][4] += a[i] * wB.x; acc[i][5] += a[i] * wB.y;
            acc[i][6] += a[i] * wB.z; acc[i][7] += a[i] * wB.w;
        }
    }
    __syncthreads();

    // write relu(hidden) back into sH (reuse)
#pragma unroll
    for (int i = 0; i < 4; i++) {
        float4 vA = make_float4(fmaxf(acc[i][0], 0.f), fmaxf(acc[i][1], 0.f),
                                fmaxf(acc[i][2], 0.f), fmaxf(acc[i][3], 0.f));
        float4 vB = make_float4(fmaxf(acc[i][4], 0.f), fmaxf(acc[i][5], 0.f),
                                fmaxf(acc[i][6], 0.f), fmaxf(acc[i][7], 0.f));
        *(float4*)&sH[(n0 + i) * SH_PAD + j0] = vA;
        *(float4*)&sH[(n0 + i) * SH_PAD + j0 + 4] = vB;
    }
    __syncthreads();

    // ---- layer 2: f = hidden @ W2 + b2 ----
    int dg = tid & 15;
    int d0 = dg * 4;
    float f[4][4];
#pragma unroll
    for (int i = 0; i < 4; i++)
#pragma unroll
        for (int u = 0; u < 4; u++) f[i][u] = sB2[d0 + u];

#pragma unroll 4
    for (int k = 0; k < HID; k++) {
        float a0 = sH[(n0 + 0) * SH_PAD + k];
        float a1 = sH[(n0 + 1) * SH_PAD + k];
        float a2 = sH[(n0 + 2) * SH_PAD + k];
        float a3 = sH[(n0 + 3) * SH_PAD + k];
        float4 wv = *(const float4*)&sW2[k * DIM + d0];
        float a[4] = {a0, a1, a2, a3};
#pragma unroll
        for (int i = 0; i < 4; i++) {
            f[i][0] += a[i] * wv.x; f[i][1] += a[i] * wv.y;
            f[i][2] += a[i] * wv.z; f[i][3] += a[i] * wv.w;
        }
    }
#pragma unroll
    for (int i = 0; i < 4; i++)
        *(float4*)&sF[(n0 + i) * DIM + d0] =
            make_float4(f[i][0], f[i][1], f[i][2], f[i][3]);
    __syncthreads();

    // ---- epilogue: x += DT*(f-x); e += DT*(-e/TAU + x_new); zero msg ----
    for (int i = tid; i < NT * DIM; i += NTH) {
        int n = i >> 6;
        int node = base + n;
        if (node < N_NODES) {
            int d = i & 63;
            int gi = node * DIM + d;
            float xv = g_x[gi];
            float fv = sF[n * DIM + d];
            float xn = xv + DT * (fv - xv);
            g_x[gi] = xn;
            float ev = g_e[gi];
            g_e[gi] = ev + DT * (xn - ev * (1.0f / TAU));
            g_msg[gi] = 0.0f;
        }
    }
}

// ---------------- output: [x (3.2M) | w (0.8M)] -----------------------------------
__global__ void finalize_kernel(float* __restrict__ out) {
    int i = blockIdx.x * blockDim.x + threadIdx.x;
    if (i < N_NODES * DIM) out[i] = g_x[i];
    else if (i < N_NODES * DIM + N_EDGES) out[i] = g_w[i - N_NODES * DIM];
}

// ---------------- launch ------------------------------------------------------------
extern "C" void kernel_launch(void* const* d_in, const int* in_sizes, int n_in,
                              void* d_out, int out_size) {
    const float* x_in  = (const float*)d_in[0];
    const void*  ei    = d_in[1];
    const float* ea    = (const float*)d_in[2];
    const float* etap  = (const float*)d_in[3];
    const float* etam  = (const float*)d_in[4];
    const float* W1    = (const float*)d_in[5];
    const float* b1    = (const float*)d_in[6];
    const float* W2    = (const float*)d_in[7];
    const float* b2    = (const float*)d_in[8];

    cudaFuncSetAttribute(node_kernel, cudaFuncAttributeMaxDynamicSharedMemorySize,
                         SMEM_BYTES);

    const int EBLK = (N_EDGES * 16) / 256;            // 50000, exact
    const int NBLK = (N_NODES + NT - 1) / NT;         // 391

    detect_kernel<<<1, 32>>>((const int*)ei);
    convert_kernel<<<(N_EDGES + 255) / 256, 256>>>(ei, ea);
    init_nodes_kernel<<<(N_NODES * DIM + 255) / 256, 256>>>(x_in);

    // step 0: messages only (no plasticity yet)
    edge_kernel<false, true><<<EBLK, 256>>>(etap, etam);
    node_kernel<<<NBLK, NTH, SMEM_BYTES>>>(W1, b1, W2, b2);

    // steps 1..9: plasticity of previous step fused with this step's messages
    for (int t = 1; t < N_STEPS; t++) {
        edge_kernel<true, true><<<EBLK, 256>>>(etap, etam);
        node_kernel<<<NBLK, NTH, SMEM_BYTES>>>(W1, b1, W2, b2);
    }
    // final plasticity (w_10), no messages needed
    edge_kernel<true, false><<<EBLK, 256>>>(etap, etam);

    finalize_kernel<<<(N_NODES * DIM + N_EDGES + 255) / 256, 256>>>((float*)d_out);
}